// round 1
// baseline (speedup 1.0000x reference)
#include <cuda_runtime.h>
#include <cuda_bf16.h>

#define F 128
#define MAXN 100000
#define MAXE 640000

// Scratch (static device allocations are allowed; cudaMalloc is not)
__device__ float g_buf1[(size_t)MAXN * F];   // xw scratch
__device__ float g_buf2[(size_t)MAXN * F];   // h (post layer-1) scratch
__device__ float g_dinv[MAXN];
__device__ int   g_deg[MAXN];
__device__ int   g_rowptr[MAXN + 1];
__device__ int   g_cursor[MAXN];
__device__ int   g_adj[MAXE];
__device__ int   g_bsums[1024];
__device__ int   g_is64;

// ---------------------------------------------------------------------------
// Edge-index dtype detection: jax emits int32 unless x64 is enabled. If the
// buffer is int64 (little-endian, values < 2^31), every odd 32-bit word of the
// first 128 pairs is 0. Random node ids make a false positive vanishingly rare.
// ---------------------------------------------------------------------------
__global__ void k_detect(const int* ei, int E) {
    if (blockIdx.x == 0 && threadIdx.x == 0) {
        int is64 = 1;
        int n = (E < 128) ? E : 128;
        for (int i = 0; i < n; i++) {
            if (ei[2 * i + 1] != 0) { is64 = 0; break; }
        }
        g_is64 = is64;
    }
}

__device__ __forceinline__ int edge_row(const int* ei, int E, int e) {
    return g_is64 ? ei[2 * e] : ei[e];
}
__device__ __forceinline__ int edge_col(const int* ei, int E, int e) {
    return g_is64 ? ei[2 * E + 2 * e] : ei[E + e];
}

// ---------------------------------------------------------------------------
// Degree / dinv
// ---------------------------------------------------------------------------
__global__ void k_init_deg(int N) {
    int i = blockIdx.x * blockDim.x + threadIdx.x;
    if (i < N) g_deg[i] = 1;  // self-loop
}

__global__ void k_count(const int* ei, int E) {
    int e = blockIdx.x * blockDim.x + threadIdx.x;
    if (e < E) atomicAdd(&g_deg[edge_col(ei, E, e)], 1);
}

__global__ void k_dinv(int N) {
    int i = blockIdx.x * blockDim.x + threadIdx.x;
    if (i < N) g_dinv[i] = rsqrtf((float)g_deg[i]);
}

// ---------------------------------------------------------------------------
// Exclusive scan of (deg-1) -> rowptr. CHUNK=1024 per block, 256 threads.
// ---------------------------------------------------------------------------
__global__ void k_scanA(int N) {
    __shared__ int s[256];
    int t = threadIdx.x;
    int base = blockIdx.x * 1024;
    int v[4];
    int run = 0;
#pragma unroll
    for (int j = 0; j < 4; j++) {
        int idx = base + t * 4 + j;
        int c = (idx < N) ? (g_deg[idx] - 1) : 0;
        v[j] = run;
        run += c;
    }
    s[t] = run;
    __syncthreads();
#pragma unroll
    for (int off = 1; off < 256; off <<= 1) {
        int x = (t >= off) ? s[t - off] : 0;
        __syncthreads();
        s[t] += x;
        __syncthreads();
    }
    if (t == 255) g_bsums[blockIdx.x] = s[255];
    int ex = (t > 0) ? s[t - 1] : 0;
#pragma unroll
    for (int j = 0; j < 4; j++) {
        int idx = base + t * 4 + j;
        if (idx < N) g_rowptr[idx] = ex + v[j];
    }
}

__global__ void k_scanB(int nb, int E, int N) {
    __shared__ int s[1024];
    int t = threadIdx.x;
    s[t] = (t < nb) ? g_bsums[t] : 0;
    __syncthreads();
    for (int off = 1; off < 1024; off <<= 1) {
        int x = (t >= off) ? s[t - off] : 0;
        __syncthreads();
        s[t] += x;
        __syncthreads();
    }
    if (t < nb) g_bsums[t] = (t > 0) ? s[t - 1] : 0;
    if (t == 0) g_rowptr[N] = E;
}

__global__ void k_scanC(int N) {
    int off = g_bsums[blockIdx.x];
    int t = threadIdx.x;
    int base = blockIdx.x * 1024;
#pragma unroll
    for (int j = 0; j < 4; j++) {
        int idx = base + t * 4 + j;
        if (idx < N) {
            int r = g_rowptr[idx] + off;
            g_rowptr[idx] = r;
            g_cursor[idx] = r;
        }
    }
}

__global__ void k_fill(const int* ei, int E) {
    int e = blockIdx.x * blockDim.x + threadIdx.x;
    if (e >= E) return;
    int r = edge_row(ei, E, e);
    int c = edge_col(ei, E, e);
    int p = atomicAdd(&g_cursor[c], 1);
    g_adj[p] = r;
}

// ---------------------------------------------------------------------------
// GEMM: C[N,128] = A[N,128] * W[128,128]  (fp32 SIMT, register tiled)
// Block: 256 threads, 64 rows x 128 cols per block. Thread: 8 rows x 4 cols.
// ---------------------------------------------------------------------------
__global__ void __launch_bounds__(256) k_gemm(const float* __restrict__ A,
                                              const float* __restrict__ W,
                                              float* __restrict__ C, int N) {
    __shared__ float Ws[8][128];  // W k-slab
    __shared__ float As[8][68];   // A tile, transposed; stride 68 avoids bank conflicts
    int t = threadIdx.x;
    int rowBase = blockIdx.x * 64;
    int cg = t & 31;   // col quad 0..31 -> cols cg*4..cg*4+3
    int rg = t >> 5;   // row group 0..7 -> rows rg*8..rg*8+7
    int r0 = rg * 8;

    float acc[8][4];
#pragma unroll
    for (int i = 0; i < 8; i++)
#pragma unroll
        for (int j = 0; j < 4; j++) acc[i][j] = 0.0f;

    for (int k0 = 0; k0 < 128; k0 += 8) {
        // load W slab: 8 x 128 floats, float4 per thread, coalesced
        {
            int kk = t >> 5;
            int c4 = (t & 31) * 4;
            *(float4*)&Ws[kk][c4] = *(const float4*)&W[(k0 + kk) * 128 + c4];
        }
        // load A tile transposed: 64 rows x 8 k
#pragma unroll
        for (int j = 0; j < 2; j++) {
            int idx = t + j * 256;
            int rr = idx >> 3;
            int kx = idx & 7;
            int grow = rowBase + rr;
            float v = (grow < N) ? A[(size_t)grow * 128 + k0 + kx] : 0.0f;
            As[kx][rr] = v;
        }
        __syncthreads();
#pragma unroll
        for (int kk = 0; kk < 8; kk++) {
            float4 a01 = *(float4*)&As[kk][r0];
            float4 a23 = *(float4*)&As[kk][r0 + 4];
            float4 b = *(float4*)&Ws[kk][cg * 4];
            float a[8] = {a01.x, a01.y, a01.z, a01.w, a23.x, a23.y, a23.z, a23.w};
#pragma unroll
            for (int i = 0; i < 8; i++) {
                acc[i][0] += a[i] * b.x;
                acc[i][1] += a[i] * b.y;
                acc[i][2] += a[i] * b.z;
                acc[i][3] += a[i] * b.w;
            }
        }
        __syncthreads();
    }
#pragma unroll
    for (int i = 0; i < 8; i++) {
        int grow = rowBase + r0 + i;
        if (grow < N) {
            float4 o = make_float4(acc[i][0], acc[i][1], acc[i][2], acc[i][3]);
            *(float4*)&C[(size_t)grow * 128 + cg * 4] = o;
        }
    }
}

// ---------------------------------------------------------------------------
// Aggregation: one warp per node. out[c] = sum_{e: col=c} xw[row]*dinv[r]*dinv[c]
//              + dinv[c]^2 * xw[c] + bias  (optionally relu)
// Each lane owns one float4 of the 128-float row.
// ---------------------------------------------------------------------------
__global__ void __launch_bounds__(256) k_agg(const float* __restrict__ XW,
                                             const float* __restrict__ bias,
                                             float* __restrict__ out, int N,
                                             int do_relu) {
    int warp = (blockIdx.x * blockDim.x + threadIdx.x) >> 5;
    int lane = threadIdx.x & 31;
    if (warp >= N) return;
    int node = warp;
    float dc = g_dinv[node];

    const float4* selfrow = (const float4*)(XW + (size_t)node * F);
    float4 v = selfrow[lane];
    float w = dc * dc;
    float4 acc;
    acc.x = v.x * w;
    acc.y = v.y * w;
    acc.z = v.z * w;
    acc.w = v.w * w;

    int p = g_rowptr[node];
    int end = g_rowptr[node + 1];
    for (; p < end; p++) {
        int src = g_adj[p];
        float nrm = g_dinv[src] * dc;
        float4 u = ((const float4*)(XW + (size_t)src * F))[lane];
        acc.x += u.x * nrm;
        acc.y += u.y * nrm;
        acc.z += u.z * nrm;
        acc.w += u.w * nrm;
    }

    float4 b = ((const float4*)bias)[lane];
    acc.x += b.x; acc.y += b.y; acc.z += b.z; acc.w += b.w;
    if (do_relu) {
        acc.x = fmaxf(acc.x, 0.0f);
        acc.y = fmaxf(acc.y, 0.0f);
        acc.z = fmaxf(acc.z, 0.0f);
        acc.w = fmaxf(acc.w, 0.0f);
    }
    ((float4*)(out + (size_t)node * F))[lane] = acc;
}

// ---------------------------------------------------------------------------
extern "C" void kernel_launch(void* const* d_in, const int* in_sizes, int n_in,
                              void* d_out, int out_size) {
    const float* x = (const float*)d_in[0];
    const int* ei = (const int*)d_in[1];  // int32 view; dtype detected on device
    const float* W1 = (const float*)d_in[2];
    const float* b1 = (const float*)d_in[3];
    const float* W2 = (const float*)d_in[4];
    const float* b2 = (const float*)d_in[5];
    float* out = (float*)d_out;

    int N = in_sizes[0] / F;
    int E = in_sizes[1] / 2;

    float *buf1, *buf2;
    cudaGetSymbolAddress((void**)&buf1, g_buf1);
    cudaGetSymbolAddress((void**)&buf2, g_buf2);

    int nb = (N + 1023) / 1024;

    k_detect<<<1, 32>>>(ei, E);
    k_init_deg<<<(N + 255) / 256, 256>>>(N);
    k_count<<<(E + 255) / 256, 256>>>(ei, E);
    k_dinv<<<(N + 255) / 256, 256>>>(N);
    k_scanA<<<nb, 256>>>(N);
    k_scanB<<<1, 1024>>>(nb, E, N);
    k_scanC<<<nb, 256>>>(N);
    k_fill<<<(E + 255) / 256, 256>>>(ei, E);

    int gemm_grid = (N + 63) / 64;
    int agg_grid = (N + 7) / 8;

    // Layer 1
    k_gemm<<<gemm_grid, 256>>>(x, W1, buf1, N);
    k_agg<<<agg_grid, 256>>>(buf1, b1, buf2, N, 1);
    // Layer 2
    k_gemm<<<gemm_grid, 256>>>(buf2, W2, buf1, N);
    k_agg<<<agg_grid, 256>>>(buf1, b2, out, N, 0);
}

// round 4
// speedup vs baseline: 1.4218x; 1.4218x over previous
#include <cuda_runtime.h>
#include <cuda_bf16.h>
#include <cstdint>

#define F 128
#define MAXN 100000
#define MAXE 640000
#define SPITCH 136   // smem row pitch in floats (128 + 8 pad -> conflict-free frag loads)

// Scratch (static device allocations are allowed; cudaMalloc is not)
__device__ float g_buf1[(size_t)MAXN * F];   // xw scratch
__device__ float g_buf2[(size_t)MAXN * F];   // h (post layer-1) scratch
__device__ float g_wf1[F * F];               // W1 fragment-swizzled (tf32)
__device__ float g_wf2[F * F];               // W2 fragment-swizzled (tf32)
__device__ float g_dinv[MAXN];
__device__ int   g_deg[MAXN];
__device__ int   g_rowptr[MAXN + 1];
__device__ int   g_cursor[MAXN];
__device__ int   g_adj[MAXE];
__device__ int   g_bsums[1024];
__device__ int   g_is64;

// ---------------------------------------------------------------------------
// helpers
// ---------------------------------------------------------------------------
__device__ __forceinline__ uint32_t f2tf32(float x) {
    uint32_t y;
    asm("cvt.rna.tf32.f32 %0, %1;" : "=r"(y) : "f"(x));
    return y;
}

__device__ __forceinline__ void mma_tf32(float* c, const uint32_t* a, const uint32_t* b) {
    asm volatile(
        "mma.sync.aligned.m16n8k8.row.col.f32.tf32.tf32.f32 "
        "{%0,%1,%2,%3}, {%4,%5,%6,%7}, {%8,%9}, {%0,%1,%2,%3};"
        : "+f"(c[0]), "+f"(c[1]), "+f"(c[2]), "+f"(c[3])
        : "r"(a[0]), "r"(a[1]), "r"(a[2]), "r"(a[3]), "r"(b[0]), "r"(b[1]));
}

// ---------------------------------------------------------------------------
// Edge-index dtype detection: jax emits int32 unless x64 is enabled. If int64
// (little-endian, ids < 2^31), every odd 32-bit word of the first pairs is 0.
// ---------------------------------------------------------------------------
__global__ void k_detect(const int* ei, int E) {
    if (blockIdx.x == 0 && threadIdx.x == 0) {
        int is64 = 1;
        int n = (E < 128) ? E : 128;
        for (int i = 0; i < n; i++) {
            if (ei[2 * i + 1] != 0) { is64 = 0; break; }
        }
        g_is64 = is64;
    }
}

__device__ __forceinline__ int edge_row(const int* ei, int E, int e) {
    return g_is64 ? ei[2 * e] : ei[e];
}
__device__ __forceinline__ int edge_col(const int* ei, int E, int e) {
    return g_is64 ? ei[2 * E + 2 * e] : ei[E + e];
}

// ---------------------------------------------------------------------------
// Degree / dinv
// ---------------------------------------------------------------------------
__global__ void k_init_deg(int N) {
    int i = blockIdx.x * blockDim.x + threadIdx.x;
    if (i < N) g_deg[i] = 1;  // self-loop
}

__global__ void k_count(const int* ei, int E) {
    int e = blockIdx.x * blockDim.x + threadIdx.x;
    if (e < E) atomicAdd(&g_deg[edge_col(ei, E, e)], 1);
}

__global__ void k_dinv(int N) {
    int i = blockIdx.x * blockDim.x + threadIdx.x;
    if (i < N) g_dinv[i] = rsqrtf((float)g_deg[i]);
}

// ---------------------------------------------------------------------------
// Exclusive scan of (deg-1) -> rowptr. CHUNK=1024 per block, 256 threads.
// ---------------------------------------------------------------------------
__global__ void k_scanA(int N) {
    __shared__ int s[256];
    int t = threadIdx.x;
    int base = blockIdx.x * 1024;
    int v[4];
    int run = 0;
#pragma unroll
    for (int j = 0; j < 4; j++) {
        int idx = base + t * 4 + j;
        int c = (idx < N) ? (g_deg[idx] - 1) : 0;
        v[j] = run;
        run += c;
    }
    s[t] = run;
    __syncthreads();
#pragma unroll
    for (int off = 1; off < 256; off <<= 1) {
        int x = (t >= off) ? s[t - off] : 0;
        __syncthreads();
        s[t] += x;
        __syncthreads();
    }
    if (t == 255) g_bsums[blockIdx.x] = s[255];
    int ex = (t > 0) ? s[t - 1] : 0;
#pragma unroll
    for (int j = 0; j < 4; j++) {
        int idx = base + t * 4 + j;
        if (idx < N) g_rowptr[idx] = ex + v[j];
    }
}

__global__ void k_scanB(int nb, int E, int N) {
    __shared__ int s[1024];
    int t = threadIdx.x;
    s[t] = (t < nb) ? g_bsums[t] : 0;
    __syncthreads();
    for (int off = 1; off < 1024; off <<= 1) {
        int x = (t >= off) ? s[t - off] : 0;
        __syncthreads();
        s[t] += x;
        __syncthreads();
    }
    if (t < nb) g_bsums[t] = (t > 0) ? s[t - 1] : 0;
    if (t == 0) g_rowptr[N] = E;
}

__global__ void k_scanC(int N) {
    int off = g_bsums[blockIdx.x];
    int t = threadIdx.x;
    int base = blockIdx.x * 1024;
#pragma unroll
    for (int j = 0; j < 4; j++) {
        int idx = base + t * 4 + j;
        if (idx < N) {
            int r = g_rowptr[idx] + off;
            g_rowptr[idx] = r;
            g_cursor[idx] = r;
        }
    }
}

__global__ void k_fill(const int* ei, int E) {
    int e = blockIdx.x * blockDim.x + threadIdx.x;
    if (e >= E) return;
    int r = edge_row(ei, E, e);
    int c = edge_col(ei, E, e);
    int p = atomicAdd(&g_cursor[c], 1);
    g_adj[p] = r;
}

// ---------------------------------------------------------------------------
// W preprocessing: W[k][n] row-major -> fragment-swizzled tf32 layout
// Wf[n*128 + ks*8 + tig*2 + half]  where k = ks*8 + half*4 + tig
// so a float2 at (n, ks, tig) = { W[ks*8+tig][n], W[ks*8+tig+4][n] } = (b0,b1)
// ---------------------------------------------------------------------------
__global__ void k_wprep(const float* __restrict__ W, float* __restrict__ Wf) {
    int idx = blockIdx.x * blockDim.x + threadIdx.x;  // 16384
    if (idx < F * F) {
        int k = idx >> 7;
        int n = idx & 127;
        uint32_t v = f2tf32(W[idx]);
        int pos = n * 128 + ((k >> 3) << 3) + ((k & 3) << 1) + ((k >> 2) & 1);
        Wf[pos] = __uint_as_float(v);
    }
}

// ---------------------------------------------------------------------------
// Tensor-core GEMM: C[N,128] = A[N,128] * W[128,128], tf32 mma.sync m16n8k8.
// Block: 256 threads (8 warps), tile 128 rows x 128 cols.
// Warp: 32 rows x 64 cols = 2 m-tiles x 8 n-tiles.
// Smem: As[128][136], Ws[128][136] in fragment-ready layout (conflict-free).
// ---------------------------------------------------------------------------
__global__ void __launch_bounds__(256) k_gemm_tc(const float* __restrict__ A,
                                                 const float* __restrict__ Wf,
                                                 float* __restrict__ C, int N) {
    extern __shared__ float sm[];
    float* As = sm;                 // 128 * SPITCH
    float* Ws = sm + 128 * SPITCH;  // 128 * SPITCH
    int t = threadIdx.x;
    int rowBase = blockIdx.x * 128;

    // Stage W fragments (already swizzled+tf32 in global; straight copy w/ pad)
#pragma unroll
    for (int i = 0; i < 16; i++) {
        int lin = t + i * 256;       // float4 index, 4096 total
        int n = lin >> 5;
        int c4 = lin & 31;
        float4 v = *(const float4*)&Wf[n * 128 + c4 * 4];
        *(float4*)&Ws[n * SPITCH + c4 * 4] = v;
    }
    // Stage A tile with swizzle + tf32 convert
#pragma unroll
    for (int i = 0; i < 16; i++) {
        int lin = t + i * 256;
        int r = lin >> 5;
        int c4 = lin & 31;
        int grow = rowBase + r;
        float4 v = make_float4(0.f, 0.f, 0.f, 0.f);
        if (grow < N) v = *(const float4*)&A[(size_t)grow * F + c4 * 4];
        int k0 = c4 * 4;  // k0 % 4 == 0
        int base = r * SPITCH + ((k0 >> 3) << 3) + ((k0 >> 2) & 1);
        As[base + 0] = __uint_as_float(f2tf32(v.x));
        As[base + 2] = __uint_as_float(f2tf32(v.y));
        As[base + 4] = __uint_as_float(f2tf32(v.z));
        As[base + 6] = __uint_as_float(f2tf32(v.w));
    }
    __syncthreads();

    int wid = t >> 5;
    int lane = t & 31;
    int g = lane >> 2;   // group id (rows of A frag / cols of B frag)
    int tig = lane & 3;  // thread in group (k index)
    int wm = (wid & 3) * 32;   // warp m offset within block tile
    int wn = (wid >> 2) * 64;  // warp n offset

    float acc[2][8][4];
#pragma unroll
    for (int mt = 0; mt < 2; mt++)
#pragma unroll
        for (int nt = 0; nt < 8; nt++)
#pragma unroll
            for (int j = 0; j < 4; j++) acc[mt][nt][j] = 0.0f;

#pragma unroll
    for (int ks = 0; ks < 16; ks++) {
        uint32_t bf[8][2];
#pragma unroll
        for (int nt = 0; nt < 8; nt++) {
            float2 v = *(float2*)&Ws[(wn + nt * 8 + g) * SPITCH + ks * 8 + tig * 2];
            bf[nt][0] = __float_as_uint(v.x);
            bf[nt][1] = __float_as_uint(v.y);
        }
        uint32_t af[2][4];
#pragma unroll
        for (int mt = 0; mt < 2; mt++) {
            int r0 = wm + mt * 16 + g;
            float2 lo = *(float2*)&As[r0 * SPITCH + ks * 8 + tig * 2];
            float2 hi = *(float2*)&As[(r0 + 8) * SPITCH + ks * 8 + tig * 2];
            af[mt][0] = __float_as_uint(lo.x);  // A[g   ][tig  ]
            af[mt][1] = __float_as_uint(hi.x);  // A[g+8 ][tig  ]
            af[mt][2] = __float_as_uint(lo.y);  // A[g   ][tig+4]
            af[mt][3] = __float_as_uint(hi.y);  // A[g+8 ][tig+4]
        }
#pragma unroll
        for (int mt = 0; mt < 2; mt++)
#pragma unroll
            for (int nt = 0; nt < 8; nt++) mma_tf32(acc[mt][nt], af[mt], bf[nt]);
    }

    // Write out: c0/c1 = row g, cols 2*tig, 2*tig+1; c2/c3 = row g+8
#pragma unroll
    for (int mt = 0; mt < 2; mt++) {
#pragma unroll
        for (int half = 0; half < 2; half++) {
            int r = rowBase + wm + mt * 16 + g + half * 8;
            if (r < N) {
#pragma unroll
                for (int nt = 0; nt < 8; nt++) {
                    float2 o = make_float2(acc[mt][nt][half * 2],
                                           acc[mt][nt][half * 2 + 1]);
                    *(float2*)&C[(size_t)r * F + wn + nt * 8 + tig * 2] = o;
                }
            }
        }
    }
}

// ---------------------------------------------------------------------------
// Aggregation: one warp per node (gather over CSR), each lane owns one float4.
// ---------------------------------------------------------------------------
__global__ void __launch_bounds__(256) k_agg(const float* __restrict__ XW,
                                             const float* __restrict__ bias,
                                             float* __restrict__ out, int N,
                                             int do_relu) {
    int warp = (blockIdx.x * blockDim.x + threadIdx.x) >> 5;
    int lane = threadIdx.x & 31;
    if (warp >= N) return;
    int node = warp;
    float dc = g_dinv[node];

    const float4* selfrow = (const float4*)(XW + (size_t)node * F);
    float4 v = selfrow[lane];
    float w = dc * dc;
    float4 acc;
    acc.x = v.x * w;
    acc.y = v.y * w;
    acc.z = v.z * w;
    acc.w = v.w * w;

    int p = g_rowptr[node];
    int end = g_rowptr[node + 1];
    for (; p < end; p++) {
        int src = g_adj[p];
        float nrm = g_dinv[src] * dc;
        float4 u = ((const float4*)(XW + (size_t)src * F))[lane];
        acc.x += u.x * nrm;
        acc.y += u.y * nrm;
        acc.z += u.z * nrm;
        acc.w += u.w * nrm;
    }

    float4 b = ((const float4*)bias)[lane];
    acc.x += b.x; acc.y += b.y; acc.z += b.z; acc.w += b.w;
    if (do_relu) {
        acc.x = fmaxf(acc.x, 0.0f);
        acc.y = fmaxf(acc.y, 0.0f);
        acc.z = fmaxf(acc.z, 0.0f);
        acc.w = fmaxf(acc.w, 0.0f);
    }
    ((float4*)(out + (size_t)node * F))[lane] = acc;
}

// ---------------------------------------------------------------------------
extern "C" void kernel_launch(void* const* d_in, const int* in_sizes, int n_in,
                              void* d_out, int out_size) {
    const float* x = (const float*)d_in[0];
    const int* ei = (const int*)d_in[1];  // int32 view; dtype detected on device
    const float* W1 = (const float*)d_in[2];
    const float* b1 = (const float*)d_in[3];
    const float* W2 = (const float*)d_in[4];
    const float* b2 = (const float*)d_in[5];
    float* out = (float*)d_out;

    int N = in_sizes[0] / F;
    int E = in_sizes[1] / 2;

    float *buf1, *buf2, *wf1, *wf2;
    cudaGetSymbolAddress((void**)&buf1, g_buf1);
    cudaGetSymbolAddress((void**)&buf2, g_buf2);
    cudaGetSymbolAddress((void**)&wf1, g_wf1);
    cudaGetSymbolAddress((void**)&wf2, g_wf2);

    const int smem_bytes = 2 * 128 * SPITCH * sizeof(float);  // 139264
    cudaFuncSetAttribute(k_gemm_tc, cudaFuncAttributeMaxDynamicSharedMemorySize,
                         smem_bytes);

    int nb = (N + 1023) / 1024;

    k_detect<<<1, 32>>>(ei, E);
    k_wprep<<<(F * F + 255) / 256, 256>>>(W1, wf1);
    k_wprep<<<(F * F + 255) / 256, 256>>>(W2, wf2);
    k_init_deg<<<(N + 255) / 256, 256>>>(N);
    k_count<<<(E + 255) / 256, 256>>>(ei, E);
    k_dinv<<<(N + 255) / 256, 256>>>(N);
    k_scanA<<<nb, 256>>>(N);
    k_scanB<<<1, 1024>>>(nb, E, N);
    k_scanC<<<nb, 256>>>(N);
    k_fill<<<(E + 255) / 256, 256>>>(ei, E);

    int gemm_grid = (N + 127) / 128;
    int agg_grid = (N + 7) / 8;

    // Layer 1
    k_gemm_tc<<<gemm_grid, 256, smem_bytes>>>(x, wf1, buf1, N);
    k_agg<<<agg_grid, 256>>>(buf1, b1, buf2, N, 1);
    // Layer 2
    k_gemm_tc<<<gemm_grid, 256, smem_bytes>>>(buf2, wf2, buf1, N);
    k_agg<<<agg_grid, 256>>>(buf1, b2, out, N, 0);
}

// round 5
// speedup vs baseline: 1.6027x; 1.1272x over previous
#include <cuda_runtime.h>
#include <cuda_bf16.h>
#include <cstdint>

#define F 128
#define MAXN 100000
#define MAXE 640000
#define SPITCH 136   // Ws smem pitch (floats)
#define APITCH 132   // As smem pitch (floats): 4g+tig distinct banks -> conflict-free
#define GEMM_GRID 152

// Scratch (static device allocations are allowed; cudaMalloc is not)
__device__ float g_buf1[(size_t)MAXN * F];
__device__ float g_buf2[(size_t)MAXN * F];
__device__ float g_wf1[F * F];               // W1 fragment-swizzled (tf32, RNA)
__device__ float g_wf2[F * F];
__device__ float g_dinv[MAXN];
__device__ int   g_deg[MAXN];
__device__ int   g_rowptr[MAXN + 1];
__device__ int   g_cursor[MAXN];
__device__ int   g_adj[MAXE];
__device__ int   g_bsums[1024];
__device__ int   g_is64;

// ---------------------------------------------------------------------------
__device__ __forceinline__ uint32_t f2tf32(float x) {
    uint32_t y;
    asm("cvt.rna.tf32.f32 %0, %1;" : "=r"(y) : "f"(x));
    return y;
}

__device__ __forceinline__ void mma_tf32(float* c, const uint32_t* a, const uint32_t* b) {
    asm volatile(
        "mma.sync.aligned.m16n8k8.row.col.f32.tf32.tf32.f32 "
        "{%0,%1,%2,%3}, {%4,%5,%6,%7}, {%8,%9}, {%0,%1,%2,%3};"
        : "+f"(c[0]), "+f"(c[1]), "+f"(c[2]), "+f"(c[3])
        : "r"(a[0]), "r"(a[1]), "r"(a[2]), "r"(a[3]), "r"(b[0]), "r"(b[1]));
}

__device__ __forceinline__ void cp16(uint32_t dst, const void* src, int sz) {
    asm volatile("cp.async.cg.shared.global [%0], [%1], 16, %2;"
                 :: "r"(dst), "l"(src), "r"(sz));
}
__device__ __forceinline__ void cp_commit() {
    asm volatile("cp.async.commit_group;");
}
template <int NN>
__device__ __forceinline__ void cp_wait() {
    asm volatile("cp.async.wait_group %0;" :: "n"(NN));
}

__device__ __forceinline__ int edge_row(const int* ei, int E, int e) {
    return g_is64 ? ei[2 * e] : ei[e];
}
__device__ __forceinline__ int edge_col(const int* ei, int E, int e) {
    return g_is64 ? ei[2 * E + 2 * e] : ei[E + e];
}

// ---------------------------------------------------------------------------
// Fused prep: block 0 = parallel int64/int32 detect; blocks 1..128 = W1/W2
// fragment-swizzle + tf32 (RNA); blocks 129.. = deg init (self-loop).
// ---------------------------------------------------------------------------
__global__ void k_prep0(const int* ei, int E,
                        const float* __restrict__ W1,
                        const float* __restrict__ W2, int N) {
    int b = blockIdx.x;
    int t = threadIdx.x;
    if (b == 0) {
        __shared__ int flag;
        if (t == 0) flag = 0;
        __syncthreads();
        int n = (E < 128) ? E : 128;
        if (t < n && ei[2 * t + 1] != 0) atomicOr(&flag, 1);
        __syncthreads();
        if (t == 0) g_is64 = flag ? 0 : 1;
    } else if (b <= 128) {
        int wb = b - 1;
        const float* W = (wb < 64) ? W1 : W2;
        float* Wf = (wb < 64) ? g_wf1 : g_wf2;
        int idx = (wb & 63) * 256 + t;
        int k = idx >> 7, n = idx & 127;
        uint32_t v = f2tf32(W[idx]);
        int pos = n * 128 + ((k >> 3) << 3) + ((k & 3) << 1) + ((k >> 2) & 1);
        Wf[pos] = __uint_as_float(v);
    } else {
        int i = (b - 129) * 256 + t;
        if (i < N) g_deg[i] = 1;
    }
}

__global__ void k_count(const int* ei, int E) {
    int e = blockIdx.x * blockDim.x + threadIdx.x;
    if (e < E) atomicAdd(&g_deg[edge_col(ei, E, e)], 1);
}

// ---------------------------------------------------------------------------
// scanA also produces dinv. Exclusive scan of (deg-1) -> rowptr.
// ---------------------------------------------------------------------------
__global__ void k_scanA(int N) {
    __shared__ int s[256];
    int t = threadIdx.x;
    int base = blockIdx.x * 1024;
    int v[4];
    int run = 0;
#pragma unroll
    for (int j = 0; j < 4; j++) {
        int idx = base + t * 4 + j;
        int c = 0;
        if (idx < N) {
            int d = g_deg[idx];
            c = d - 1;
            g_dinv[idx] = rsqrtf((float)d);
        }
        v[j] = run;
        run += c;
    }
    s[t] = run;
    __syncthreads();
#pragma unroll
    for (int off = 1; off < 256; off <<= 1) {
        int x = (t >= off) ? s[t - off] : 0;
        __syncthreads();
        s[t] += x;
        __syncthreads();
    }
    if (t == 255) g_bsums[blockIdx.x] = s[255];
    int ex = (t > 0) ? s[t - 1] : 0;
#pragma unroll
    for (int j = 0; j < 4; j++) {
        int idx = base + t * 4 + j;
        if (idx < N) g_rowptr[idx] = ex + v[j];
    }
}

__global__ void k_scanB(int nb, int E, int N) {
    __shared__ int s[1024];
    int t = threadIdx.x;
    s[t] = (t < nb) ? g_bsums[t] : 0;
    __syncthreads();
    for (int off = 1; off < 1024; off <<= 1) {
        int x = (t >= off) ? s[t - off] : 0;
        __syncthreads();
        s[t] += x;
        __syncthreads();
    }
    if (t < nb) g_bsums[t] = (t > 0) ? s[t - 1] : 0;
    if (t == 0) g_rowptr[N] = E;
}

__global__ void k_scanC(int N) {
    int off = g_bsums[blockIdx.x];
    int t = threadIdx.x;
    int base = blockIdx.x * 1024;
#pragma unroll
    for (int j = 0; j < 4; j++) {
        int idx = base + t * 4 + j;
        if (idx < N) {
            int r = g_rowptr[idx] + off;
            g_rowptr[idx] = r;
            g_cursor[idx] = r;
        }
    }
}

__global__ void k_fill(const int* ei, int E) {
    int e = blockIdx.x * blockDim.x + threadIdx.x;
    if (e >= E) return;
    int r = edge_row(ei, E, e);
    int c = edge_col(ei, E, e);
    int p = atomicAdd(&g_cursor[c], 1);
    g_adj[p] = r;
}

// ---------------------------------------------------------------------------
// Persistent double-buffered tensor-core GEMM: C[N,128] = A[N,128]*W[128,128].
// 152 blocks x 256 threads. W staged once per block (pre-swizzled tf32).
// A tiles (128 rows) streamed with cp.async into a 2-deep ring; raw fp32 in
// smem, RNA-converted to tf32 at the fragment read.
// ---------------------------------------------------------------------------
__global__ void __launch_bounds__(256) k_gemm_tc(const float* __restrict__ A,
                                                 const float* __restrict__ Wf,
                                                 float* __restrict__ C, int N,
                                                 int ntiles) {
    extern __shared__ float sm[];
    float* Ws = sm;                        // 128 * SPITCH
    float* As0 = sm + 128 * SPITCH;        // 128 * APITCH
    float* As1 = As0 + 128 * APITCH;
    float* Asbuf[2] = {As0, As1};
    uint32_t AsAddr[2] = {(uint32_t)__cvta_generic_to_shared(As0),
                          (uint32_t)__cvta_generic_to_shared(As1)};
    int t = threadIdx.x;

    // Stage W (straight copy with pitch pad)
#pragma unroll
    for (int i = 0; i < 16; i++) {
        int lin = t + i * 256;
        int n = lin >> 5;
        int c4 = lin & 31;
        float4 v = *(const float4*)&Wf[n * 128 + c4 * 4];
        *(float4*)&Ws[n * SPITCH + c4 * 4] = v;
    }

    int wid = t >> 5;
    int lane = t & 31;
    int g = lane >> 2;
    int tig = lane & 3;
    int wm = (wid & 3) * 32;
    int wn = (wid >> 2) * 64;

    // Prologue: stage first tile into buffer 0
    int tile0 = blockIdx.x;
    if (tile0 < ntiles) {
        int rowBase = tile0 * 128;
#pragma unroll
        for (int i = 0; i < 16; i++) {
            int lin = t + i * 256;
            int r = lin >> 5;
            int c16 = lin & 31;
            int grow = rowBase + r;
            int cl = (grow < N) ? grow : (N - 1);
            cp16(AsAddr[0] + (uint32_t)(r * APITCH + c16 * 4) * 4,
                 A + (size_t)cl * F + c16 * 4, (grow < N) ? 16 : 0);
        }
    }
    cp_commit();

    int b = 0;
    for (int tile = tile0; tile < ntiles; tile += GEMM_GRID) {
        int next = tile + GEMM_GRID;
        if (next < ntiles) {
            int rowBase = next * 128;
            uint32_t dst = AsAddr[b ^ 1];
#pragma unroll
            for (int i = 0; i < 16; i++) {
                int lin = t + i * 256;
                int r = lin >> 5;
                int c16 = lin & 31;
                int grow = rowBase + r;
                int cl = (grow < N) ? grow : (N - 1);
                cp16(dst + (uint32_t)(r * APITCH + c16 * 4) * 4,
                     A + (size_t)cl * F + c16 * 4, (grow < N) ? 16 : 0);
            }
            cp_commit();
            cp_wait<1>();
        } else {
            cp_commit();  // empty group keeps wait semantics simple
            cp_wait<0>();
        }
        __syncthreads();  // tile data (and Ws on first iter) visible

        const float* As = Asbuf[b];
        float acc[2][8][4];
#pragma unroll
        for (int mt = 0; mt < 2; mt++)
#pragma unroll
            for (int nt = 0; nt < 8; nt++)
#pragma unroll
                for (int j = 0; j < 4; j++) acc[mt][nt][j] = 0.0f;

#pragma unroll
        for (int ks = 0; ks < 16; ks++) {
            uint32_t bf[8][2];
#pragma unroll
            for (int nt = 0; nt < 8; nt++) {
                float2 v = *(const float2*)&Ws[(wn + nt * 8 + g) * SPITCH + ks * 8 + tig * 2];
                bf[nt][0] = __float_as_uint(v.x);
                bf[nt][1] = __float_as_uint(v.y);
            }
            uint32_t af[2][4];
#pragma unroll
            for (int mt = 0; mt < 2; mt++) {
                int r0 = (wm + mt * 16 + g) * APITCH + ks * 8 + tig;
                int r1 = r0 + 8 * APITCH;
                af[mt][0] = f2tf32(As[r0]);
                af[mt][1] = f2tf32(As[r1]);
                af[mt][2] = f2tf32(As[r0 + 4]);
                af[mt][3] = f2tf32(As[r1 + 4]);
            }
#pragma unroll
            for (int mt = 0; mt < 2; mt++)
#pragma unroll
                for (int nt = 0; nt < 8; nt++) mma_tf32(acc[mt][nt], af[mt], bf[nt]);
        }

        int rowBase = tile * 128;
#pragma unroll
        for (int mt = 0; mt < 2; mt++) {
#pragma unroll
            for (int half = 0; half < 2; half++) {
                int r = rowBase + wm + mt * 16 + g + half * 8;
                if (r < N) {
#pragma unroll
                    for (int nt = 0; nt < 8; nt++) {
                        float2 o = make_float2(acc[mt][nt][half * 2],
                                               acc[mt][nt][half * 2 + 1]);
                        *(float2*)&C[(size_t)r * F + wn + nt * 8 + tig * 2] = o;
                    }
                }
            }
        }
        __syncthreads();  // done reading buf b before it becomes a prefetch target
        b ^= 1;
    }
}

// ---------------------------------------------------------------------------
// Aggregation: one warp per node (gather over CSR), each lane owns one float4.
// ---------------------------------------------------------------------------
__global__ void __launch_bounds__(256) k_agg(const float* __restrict__ XW,
                                             const float* __restrict__ bias,
                                             float* __restrict__ out, int N,
                                             int do_relu) {
    int warp = (blockIdx.x * blockDim.x + threadIdx.x) >> 5;
    int lane = threadIdx.x & 31;
    if (warp >= N) return;
    int node = warp;
    float dc = g_dinv[node];

    float4 v = ((const float4*)(XW + (size_t)node * F))[lane];
    float w = dc * dc;
    float4 acc;
    acc.x = v.x * w;
    acc.y = v.y * w;
    acc.z = v.z * w;
    acc.w = v.w * w;

    int p = g_rowptr[node];
    int end = g_rowptr[node + 1];
    for (; p < end; p++) {
        int src = g_adj[p];
        float nrm = g_dinv[src] * dc;
        float4 u = ((const float4*)(XW + (size_t)src * F))[lane];
        acc.x += u.x * nrm;
        acc.y += u.y * nrm;
        acc.z += u.z * nrm;
        acc.w += u.w * nrm;
    }

    float4 bb = ((const float4*)bias)[lane];
    acc.x += bb.x; acc.y += bb.y; acc.z += bb.z; acc.w += bb.w;
    if (do_relu) {
        acc.x = fmaxf(acc.x, 0.0f);
        acc.y = fmaxf(acc.y, 0.0f);
        acc.z = fmaxf(acc.z, 0.0f);
        acc.w = fmaxf(acc.w, 0.0f);
    }
    ((float4*)(out + (size_t)node * F))[lane] = acc;
}

// ---------------------------------------------------------------------------
extern "C" void kernel_launch(void* const* d_in, const int* in_sizes, int n_in,
                              void* d_out, int out_size) {
    const float* x = (const float*)d_in[0];
    const int* ei = (const int*)d_in[1];
    const float* W1 = (const float*)d_in[2];
    const float* b1 = (const float*)d_in[3];
    const float* W2 = (const float*)d_in[4];
    const float* b2 = (const float*)d_in[5];
    float* out = (float*)d_out;

    int N = in_sizes[0] / F;
    int E = in_sizes[1] / 2;

    float *buf1, *buf2, *wf1, *wf2;
    cudaGetSymbolAddress((void**)&buf1, g_buf1);
    cudaGetSymbolAddress((void**)&buf2, g_buf2);
    cudaGetSymbolAddress((void**)&wf1, g_wf1);
    cudaGetSymbolAddress((void**)&wf2, g_wf2);

    const int smem_bytes = (128 * SPITCH + 2 * 128 * APITCH) * sizeof(float);  // 204800
    static int attr_done = 0;
    cudaFuncSetAttribute(k_gemm_tc, cudaFuncAttributeMaxDynamicSharedMemorySize,
                         smem_bytes);
    (void)attr_done;

    int nb = (N + 1023) / 1024;
    int prep_grid = 1 + 128 + (N + 255) / 256;

    k_prep0<<<prep_grid, 256>>>(ei, E, W1, W2, N);
    k_count<<<(E + 255) / 256, 256>>>(ei, E);
    k_scanA<<<nb, 256>>>(N);
    k_scanB<<<1, 1024>>>(nb, E, N);
    k_scanC<<<nb, 256>>>(N);
    k_fill<<<(E + 255) / 256, 256>>>(ei, E);

    int ntiles = (N + 127) / 128;
    int agg_grid = (N + 7) / 8;

    // Layer 1
    k_gemm_tc<<<GEMM_GRID, 256, smem_bytes>>>(x, wf1, buf1, N, ntiles);
    k_agg<<<agg_grid, 256>>>(buf1, b1, buf2, N, 1);
    // Layer 2
    k_gemm_tc<<<GEMM_GRID, 256, smem_bytes>>>(buf2, wf2, buf1, N, ntiles);
    k_agg<<<agg_grid, 256>>>(buf1, b2, out, N, 0);
}

// round 6
// speedup vs baseline: 1.7452x; 1.0890x over previous
#include <cuda_runtime.h>
#include <cuda_fp16.h>
#include <cstdint>

#define F 128
#define MAXN 100000
#define SPITCH 136      // Ws smem pitch (floats)
#define APITCH 132      // fp32 A smem pitch (floats)
#define APITCH_H 136    // fp16 A smem pitch (halfs)
#define ELLW 64
#define GEMM_GRID 152

// Static device scratch (cudaMalloc is forbidden)
__device__ uint16_t g_xw[(size_t)MAXN * F];     // fp16 XW scratch
__device__ uint16_t g_h[(size_t)MAXN * F];      // fp16 hidden scratch
__device__ float    g_dinv[MAXN];
__device__ int      g_deg[MAXN];
__device__ int      g_ell[(size_t)MAXN * ELLW];

// ---------------------------------------------------------------------------
__device__ __forceinline__ uint32_t f2tf32(float x) {
    uint32_t y;
    asm("cvt.rna.tf32.f32 %0, %1;" : "=r"(y) : "f"(x));
    return y;
}

__device__ __forceinline__ void mma_tf32(float* c, const uint32_t* a, const uint32_t* b) {
    asm volatile(
        "mma.sync.aligned.m16n8k8.row.col.f32.tf32.tf32.f32 "
        "{%0,%1,%2,%3}, {%4,%5,%6,%7}, {%8,%9}, {%0,%1,%2,%3};"
        : "+f"(c[0]), "+f"(c[1]), "+f"(c[2]), "+f"(c[3])
        : "r"(a[0]), "r"(a[1]), "r"(a[2]), "r"(a[3]), "r"(b[0]), "r"(b[1]));
}

__device__ __forceinline__ void cp16(uint32_t dst, const void* src, int sz) {
    asm volatile("cp.async.cg.shared.global [%0], [%1], 16, %2;"
                 :: "r"(dst), "l"(src), "r"(sz));
}
__device__ __forceinline__ void cp_commit() { asm volatile("cp.async.commit_group;"); }
template <int NN>
__device__ __forceinline__ void cp_wait() {
    asm volatile("cp.async.wait_group %0;" :: "n"(NN));
}

__device__ __forceinline__ float4 h4_to_f4(uint2 v) {
    __half2 a = *(__half2*)&v.x;
    __half2 b = *(__half2*)&v.y;
    float2 fa = __half22float2(a);
    float2 fb = __half22float2(b);
    return make_float4(fa.x, fa.y, fb.x, fb.y);
}

// ---------------------------------------------------------------------------
// ELL build: per-block inline dtype detect (warp-parallel, L1-hot), then
// slot = atomicAdd(deg[col]) and direct ELL write. deg pre-zeroed by memset.
// ---------------------------------------------------------------------------
__global__ void __launch_bounds__(256) k_csr(const int* __restrict__ ei, int E) {
    __shared__ int s_is64;
    int t = threadIdx.x;
    if (t < 32) {
        int n = (E < 16) ? E : 16;
        int bad = (t < n) ? (ei[2 * t + 1] != 0) : 0;
        bad = __any_sync(0xffffffffu, bad);
        if (t == 0) s_is64 = !bad;
    }
    __syncthreads();
    int is64 = s_is64;

    int e = blockIdx.x * 256 + t;
    if (e < E) {
        int r, c;
        if (is64) {
            r = ei[2 * e];
            c = ei[2 * E + 2 * e];
        } else {
            r = ei[e];
            c = ei[E + e];
        }
        int p = atomicAdd(&g_deg[c], 1);
        if (p < ELLW) g_ell[(size_t)c * ELLW + p] = r;
    }
}

// ---------------------------------------------------------------------------
// Persistent double-buffered tensor-core GEMM: C[N,128] = A[N,128]*W[128,128].
// W swizzled+tf32-converted from raw global in the prologue (once per block).
// A tiles streamed with cp.async (2-deep ring). AT = float (layer 1 input) or
// __half (layer 2 hidden). C written fp16. Optional dinv tail (layer 1).
// ---------------------------------------------------------------------------
template <typename AT>
__global__ void __launch_bounds__(256) k_gemm_tc(const AT* __restrict__ A,
                                                 const float* __restrict__ W,
                                                 uint16_t* __restrict__ C,
                                                 int N, int ntiles, int do_dinv) {
    constexpr bool HALF_A = (sizeof(AT) == 2);
    extern __shared__ char smraw[];
    float* Ws = (float*)smraw;
    char* As0 = smraw + 128 * SPITCH * sizeof(float);
    const int abufBytes = HALF_A ? 128 * APITCH_H * 2 : 128 * APITCH * 4;
    char* As1 = As0 + abufBytes;
    char* AsPtr[2] = {As0, As1};
    uint32_t AsAddr[2] = {(uint32_t)__cvta_generic_to_shared(As0),
                          (uint32_t)__cvta_generic_to_shared(As1)};
    int t = threadIdx.x;

    // Stage W: raw fp32 -> fragment-swizzled tf32 in smem
#pragma unroll
    for (int i = 0; i < 16; i++) {
        int lin = t + i * 256;
        int k = lin >> 5;
        int n4 = (lin & 31) * 4;
        float4 v = *(const float4*)&W[k * 128 + n4];
        int kperm = ((k >> 3) << 3) + ((k & 3) << 1) + ((k >> 2) & 1);
        Ws[(n4 + 0) * SPITCH + kperm] = __uint_as_float(f2tf32(v.x));
        Ws[(n4 + 1) * SPITCH + kperm] = __uint_as_float(f2tf32(v.y));
        Ws[(n4 + 2) * SPITCH + kperm] = __uint_as_float(f2tf32(v.z));
        Ws[(n4 + 3) * SPITCH + kperm] = __uint_as_float(f2tf32(v.w));
    }

    int wid = t >> 5;
    int lane = t & 31;
    int g = lane >> 2;
    int tig = lane & 3;
    int wm = (wid & 3) * 32;
    int wn = (wid >> 2) * 64;

    auto stage = [&](uint32_t dst, int tile) {
        int rowBase = tile * 128;
        if (HALF_A) {
#pragma unroll
            for (int i = 0; i < 8; i++) {
                int lin = t + i * 256;
                int r = lin >> 4;
                int c8 = lin & 15;
                int grow = rowBase + r;
                int cl = (grow < N) ? grow : (N - 1);
                cp16(dst + (uint32_t)(r * APITCH_H + c8 * 8) * 2,
                     (const char*)A + ((size_t)cl * F + c8 * 8) * sizeof(AT),
                     (grow < N) ? 16 : 0);
            }
        } else {
#pragma unroll
            for (int i = 0; i < 16; i++) {
                int lin = t + i * 256;
                int r = lin >> 5;
                int c4 = lin & 31;
                int grow = rowBase + r;
                int cl = (grow < N) ? grow : (N - 1);
                cp16(dst + (uint32_t)(r * APITCH + c4 * 4) * 4,
                     (const char*)A + ((size_t)cl * F + c4 * 4) * sizeof(AT),
                     (grow < N) ? 16 : 0);
            }
        }
    };

    int tile0 = blockIdx.x;
    if (tile0 < ntiles) stage(AsAddr[0], tile0);
    cp_commit();

    int b = 0;
    for (int tile = tile0; tile < ntiles; tile += GEMM_GRID) {
        int next = tile + GEMM_GRID;
        if (next < ntiles) {
            stage(AsAddr[b ^ 1], next);
            cp_commit();
            cp_wait<1>();
        } else {
            cp_commit();
            cp_wait<0>();
        }
        __syncthreads();

        float acc[2][8][4];
#pragma unroll
        for (int mt = 0; mt < 2; mt++)
#pragma unroll
            for (int nt = 0; nt < 8; nt++)
#pragma unroll
                for (int j = 0; j < 4; j++) acc[mt][nt][j] = 0.0f;

#pragma unroll
        for (int ks = 0; ks < 16; ks++) {
            uint32_t bf[8][2];
#pragma unroll
            for (int nt = 0; nt < 8; nt++) {
                float2 v = *(const float2*)&Ws[(wn + nt * 8 + g) * SPITCH + ks * 8 + tig * 2];
                bf[nt][0] = __float_as_uint(v.x);
                bf[nt][1] = __float_as_uint(v.y);
            }
            uint32_t af[2][4];
#pragma unroll
            for (int mt = 0; mt < 2; mt++) {
                if (HALF_A) {
                    const __half* As = (const __half*)AsPtr[b];
                    int r0 = (wm + mt * 16 + g) * APITCH_H + ks * 8 + tig;
                    int r1 = r0 + 8 * APITCH_H;
                    // fp16 -> fp32 is exact; fp16 mantissa fits tf32 exactly
                    af[mt][0] = __float_as_uint(__half2float(As[r0]));
                    af[mt][1] = __float_as_uint(__half2float(As[r1]));
                    af[mt][2] = __float_as_uint(__half2float(As[r0 + 4]));
                    af[mt][3] = __float_as_uint(__half2float(As[r1 + 4]));
                } else {
                    const float* As = (const float*)AsPtr[b];
                    int r0 = (wm + mt * 16 + g) * APITCH + ks * 8 + tig;
                    int r1 = r0 + 8 * APITCH;
                    af[mt][0] = f2tf32(As[r0]);
                    af[mt][1] = f2tf32(As[r1]);
                    af[mt][2] = f2tf32(As[r0 + 4]);
                    af[mt][3] = f2tf32(As[r1 + 4]);
                }
            }
#pragma unroll
            for (int mt = 0; mt < 2; mt++)
#pragma unroll
                for (int nt = 0; nt < 8; nt++) mma_tf32(acc[mt][nt], af[mt], bf[nt]);
        }

        int rowBase = tile * 128;
#pragma unroll
        for (int mt = 0; mt < 2; mt++) {
#pragma unroll
            for (int half = 0; half < 2; half++) {
                int r = rowBase + wm + mt * 16 + g + half * 8;
                if (r < N) {
#pragma unroll
                    for (int nt = 0; nt < 8; nt++) {
                        __half2 hv = __floats2half2_rn(acc[mt][nt][half * 2],
                                                       acc[mt][nt][half * 2 + 1]);
                        *(__half2*)&C[(size_t)r * F + wn + nt * 8 + tig * 2] = hv;
                    }
                }
            }
        }
        __syncthreads();
        b ^= 1;
    }

    // dinv tail (layer 1 only): deg excludes self-loop -> d = deg+1
    if (do_dinv) {
        for (int i = blockIdx.x * 256 + t; i < N; i += GEMM_GRID * 256)
            g_dinv[i] = rsqrtf((float)g_deg[i] + 1.0f);
    }
}

// ---------------------------------------------------------------------------
// Aggregation: one warp per node over ELL. Indices + dinv fetched by one
// lane-cooperative load and broadcast via shfl. Rows gathered as fp16 (256B).
// ---------------------------------------------------------------------------
template <int RELU, int OUTHALF>
__global__ void __launch_bounds__(256) k_agg(const uint16_t* __restrict__ XW,
                                             const float* __restrict__ bias,
                                             void* __restrict__ outp, int N) {
    int node = (blockIdx.x * blockDim.x + threadIdx.x) >> 5;
    int lane = threadIdx.x & 31;
    if (node >= N) return;

    float dc = g_dinv[node];
    int d = g_deg[node];
    int cnt = (d < ELLW) ? d : ELLW;

    const int* nb = g_ell + (size_t)node * ELLW;
    int idx0 = (lane < cnt) ? nb[lane] : 0;
    int idx1 = (lane + 32 < cnt) ? nb[lane + 32] : 0;
    float dv0 = (lane < cnt) ? g_dinv[idx0] : 0.0f;
    float dv1 = (lane + 32 < cnt) ? g_dinv[idx1] : 0.0f;

    uint2 sv = ((const uint2*)(XW + (size_t)node * F))[lane];
    float4 s = h4_to_f4(sv);
    float w = dc * dc;
    float4 acc = make_float4(s.x * w, s.y * w, s.z * w, s.w * w);

    for (int j = 0; j < cnt; j++) {
        int src = __shfl_sync(0xffffffffu, (j < 32) ? idx0 : idx1, j & 31);
        float ds = __shfl_sync(0xffffffffu, (j < 32) ? dv0 : dv1, j & 31);
        float nrm = ds * dc;
        uint2 uv = ((const uint2*)(XW + (size_t)src * F))[lane];
        float4 u = h4_to_f4(uv);
        acc.x += u.x * nrm;
        acc.y += u.y * nrm;
        acc.z += u.z * nrm;
        acc.w += u.w * nrm;
    }

    float4 bb = ((const float4*)bias)[lane];
    acc.x += bb.x; acc.y += bb.y; acc.z += bb.z; acc.w += bb.w;
    if (RELU) {
        acc.x = fmaxf(acc.x, 0.0f);
        acc.y = fmaxf(acc.y, 0.0f);
        acc.z = fmaxf(acc.z, 0.0f);
        acc.w = fmaxf(acc.w, 0.0f);
    }
    if (OUTHALF) {
        __half2 h01 = __floats2half2_rn(acc.x, acc.y);
        __half2 h23 = __floats2half2_rn(acc.z, acc.w);
        uint2 o;
        o.x = *(uint32_t*)&h01;
        o.y = *(uint32_t*)&h23;
        ((uint2*)((uint16_t*)outp + (size_t)node * F))[lane] = o;
    } else {
        ((float4*)((float*)outp + (size_t)node * F))[lane] = acc;
    }
}

// ---------------------------------------------------------------------------
extern "C" void kernel_launch(void* const* d_in, const int* in_sizes, int n_in,
                              void* d_out, int out_size) {
    const float* x = (const float*)d_in[0];
    const int* ei = (const int*)d_in[1];
    const float* W1 = (const float*)d_in[2];
    const float* b1 = (const float*)d_in[3];
    const float* W2 = (const float*)d_in[4];
    const float* b2 = (const float*)d_in[5];
    float* out = (float*)d_out;

    int N = in_sizes[0] / F;
    int E = in_sizes[1] / 2;

    uint16_t *xwp, *hp;
    int* degp;
    cudaGetSymbolAddress((void**)&xwp, g_xw);
    cudaGetSymbolAddress((void**)&hp, g_h);
    cudaGetSymbolAddress((void**)&degp, g_deg);

    const int smem_f = (128 * SPITCH + 2 * 128 * APITCH) * sizeof(float);    // 204800
    const int smem_h = 128 * SPITCH * 4 + 2 * 128 * APITCH_H * 2;            // 139264
    cudaFuncSetAttribute(k_gemm_tc<float>,
                         cudaFuncAttributeMaxDynamicSharedMemorySize, smem_f);
    cudaFuncSetAttribute(k_gemm_tc<__half>,
                         cudaFuncAttributeMaxDynamicSharedMemorySize, smem_h);

    int ntiles = (N + 127) / 128;
    int agg_grid = (N + 7) / 8;

    cudaMemsetAsync(degp, 0, (size_t)N * sizeof(int), 0);
    k_csr<<<(E + 255) / 256, 256>>>(ei, E);

    // Layer 1
    k_gemm_tc<float><<<GEMM_GRID, 256, smem_f>>>(x, W1, xwp, N, ntiles, 1);
    k_agg<1, 1><<<agg_grid, 256>>>(xwp, b1, hp, N);
    // Layer 2
    k_gemm_tc<__half><<<GEMM_GRID, 256, smem_h>>>((const __half*)hp, W2, xwp, N,
                                                  ntiles, 0);
    k_agg<0, 0><<<agg_grid, 256>>>(xwp, b2, out, N);
}

// round 7
// speedup vs baseline: 1.8698x; 1.0714x over previous
#include <cuda_runtime.h>
#include <cuda_fp16.h>
#include <cstdint>

#define F 128
#define MAXN 100000
#define PITCH_H 136     // smem pitch in halves: 272B ≡ 4 banks mod 32 -> ldmatrix conflict-free
#define ELLW 64
#define GEMM_GRID 152

// Static device scratch (cudaMalloc is forbidden)
__device__ uint16_t g_xh[(size_t)MAXN * F];     // x converted to fp16
__device__ uint16_t g_xw[(size_t)MAXN * F];     // fp16 XW scratch
__device__ uint16_t g_h[(size_t)MAXN * F];      // fp16 hidden scratch
__device__ float    g_dinv[MAXN];
__device__ int      g_deg[MAXN];
__device__ int      g_ell[(size_t)MAXN * ELLW];

// ---------------------------------------------------------------------------
__device__ __forceinline__ void mma_f16(float* c, const uint32_t* a, const uint32_t* b) {
    asm volatile(
        "mma.sync.aligned.m16n8k16.row.col.f32.f16.f16.f32 "
        "{%0,%1,%2,%3}, {%4,%5,%6,%7}, {%8,%9}, {%0,%1,%2,%3};"
        : "+f"(c[0]), "+f"(c[1]), "+f"(c[2]), "+f"(c[3])
        : "r"(a[0]), "r"(a[1]), "r"(a[2]), "r"(a[3]), "r"(b[0]), "r"(b[1]));
}

__device__ __forceinline__ void ldsm_x4(uint32_t& r0, uint32_t& r1, uint32_t& r2,
                                        uint32_t& r3, uint32_t addr) {
    asm volatile("ldmatrix.sync.aligned.m8n8.x4.shared.b16 {%0,%1,%2,%3}, [%4];"
                 : "=r"(r0), "=r"(r1), "=r"(r2), "=r"(r3) : "r"(addr));
}

__device__ __forceinline__ void cp16(uint32_t dst, const void* src, int sz) {
    asm volatile("cp.async.cg.shared.global [%0], [%1], 16, %2;"
                 :: "r"(dst), "l"(src), "r"(sz));
}
__device__ __forceinline__ void cp_commit() { asm volatile("cp.async.commit_group;"); }
template <int NN>
__device__ __forceinline__ void cp_wait() {
    asm volatile("cp.async.wait_group %0;" :: "n"(NN));
}

__device__ __forceinline__ float4 h4_to_f4(uint2 v) {
    __half2 a = *(__half2*)&v.x;
    __half2 b = *(__half2*)&v.y;
    float2 fa = __half22float2(a);
    float2 fb = __half22float2(b);
    return make_float4(fa.x, fa.y, fb.x, fb.y);
}

// ---------------------------------------------------------------------------
// Fused: edge blocks build ELL (with inline int64/int32 detect); trailing
// blocks convert x fp32 -> fp16. deg pre-zeroed by memset.
// ---------------------------------------------------------------------------
__global__ void __launch_bounds__(256) k_csr(const int* __restrict__ ei, int E,
                                             const float* __restrict__ x,
                                             uint16_t* __restrict__ xh, int N,
                                             int EB) {
    int b = blockIdx.x;
    int t = threadIdx.x;
    if (b < EB) {
        __shared__ int s_is64;
        if (t < 32) {
            int n = (E < 16) ? E : 16;
            int bad = (t < n) ? (ei[2 * t + 1] != 0) : 0;
            bad = __any_sync(0xffffffffu, bad);
            if (t == 0) s_is64 = !bad;
        }
        __syncthreads();
        int is64 = s_is64;
        int e = b * 256 + t;
        if (e < E) {
            int r, c;
            if (is64) {
                r = ei[2 * e];
                c = ei[2 * E + 2 * e];
            } else {
                r = ei[e];
                c = ei[E + e];
            }
            int p = atomicAdd(&g_deg[c], 1);
            if (p < ELLW) g_ell[(size_t)c * ELLW + p] = r;
        }
    } else {
        int gid = (b - EB) * 256 + t;          // one float4 per thread
        int total = N * (F / 4);
        if (gid < total) {
            float4 v = ((const float4*)x)[gid];
            __half2 h01 = __floats2half2_rn(v.x, v.y);
            __half2 h23 = __floats2half2_rn(v.z, v.w);
            uint2 o;
            o.x = *(uint32_t*)&h01;
            o.y = *(uint32_t*)&h23;
            ((uint2*)xh)[gid] = o;
        }
    }
}

// ---------------------------------------------------------------------------
// Persistent double-buffered fp16 tensor-core GEMM:
// C[N,128] (fp16) = A[N,128] (fp16) * W[128,128] (fp32 -> fp16).
// mma.m16n8k16 + ldmatrix.x4 fragments. 152 blocks x 256 threads.
// W transposed to Wt[n][k] fp16 in smem once per block; A tiles streamed
// with cp.async (2-deep ring). Optional dinv tail (layer 1).
// ---------------------------------------------------------------------------
__global__ void __launch_bounds__(256) k_gemm_tc(const __half* __restrict__ A,
                                                 const float* __restrict__ W,
                                                 uint16_t* __restrict__ C,
                                                 int N, int ntiles, int do_dinv) {
    extern __shared__ char smraw[];
    __half* Wt = (__half*)smraw;                       // 128 * PITCH_H halves
    __half* As0 = (__half*)(smraw + 128 * PITCH_H * 2);
    __half* As1 = As0 + 128 * PITCH_H;
    uint32_t WtA = (uint32_t)__cvta_generic_to_shared(Wt);
    uint32_t AsA[2] = {(uint32_t)__cvta_generic_to_shared(As0),
                       (uint32_t)__cvta_generic_to_shared(As1)};
    int t = threadIdx.x;

    // Stage W: fp32 [k][n] -> fp16 Wt[n][k]
#pragma unroll
    for (int i = 0; i < 16; i++) {
        int lin = t + i * 256;             // 4096 float4 = 16384 floats
        int k = lin >> 5;
        int n4 = (lin & 31) * 4;
        float4 v = *(const float4*)&W[k * 128 + n4];
        Wt[(n4 + 0) * PITCH_H + k] = __float2half_rn(v.x);
        Wt[(n4 + 1) * PITCH_H + k] = __float2half_rn(v.y);
        Wt[(n4 + 2) * PITCH_H + k] = __float2half_rn(v.z);
        Wt[(n4 + 3) * PITCH_H + k] = __float2half_rn(v.w);
    }

    int wid = t >> 5;
    int lane = t & 31;
    int g = lane >> 2;
    int tig = lane & 3;
    int wm = (wid & 3) * 32;   // warp m offset
    int wn = (wid >> 2) * 64;  // warp n offset

    // ldmatrix per-lane base offsets (halves)
    int arow = lane & 15;
    int akoff = (lane & 16) ? 8 : 0;
    int a_off[2];
#pragma unroll
    for (int mt = 0; mt < 2; mt++)
        a_off[mt] = (wm + mt * 16 + arow) * PITCH_H + akoff;
    int brow = (lane & 7) + ((lane & 16) ? 8 : 0);
    int bkoff = (lane & 8) ? 8 : 0;
    int b_off[4];
#pragma unroll
    for (int p = 0; p < 4; p++)
        b_off[p] = (wn + p * 16 + brow) * PITCH_H + bkoff;

    auto stage = [&](uint32_t dst, int tile) {
        int rowBase = tile * 128;
#pragma unroll
        for (int i = 0; i < 8; i++) {
            int lin = t + i * 256;         // 2048 x 16B chunks
            int r = lin >> 4;
            int c8 = lin & 15;
            int grow = rowBase + r;
            int cl = (grow < N) ? grow : (N - 1);
            cp16(dst + (uint32_t)(r * PITCH_H + c8 * 8) * 2,
                 (const char*)A + ((size_t)cl * F + c8 * 8) * 2,
                 (grow < N) ? 16 : 0);
        }
    };

    int tile0 = blockIdx.x;
    if (tile0 < ntiles) stage(AsA[0], tile0);
    cp_commit();

    int b = 0;
    for (int tile = tile0; tile < ntiles; tile += GEMM_GRID) {
        int next = tile + GEMM_GRID;
        if (next < ntiles) {
            stage(AsA[b ^ 1], next);
            cp_commit();
            cp_wait<1>();
        } else {
            cp_commit();
            cp_wait<0>();
        }
        __syncthreads();

        float acc[2][8][4];
#pragma unroll
        for (int mt = 0; mt < 2; mt++)
#pragma unroll
            for (int nt = 0; nt < 8; nt++)
#pragma unroll
                for (int j = 0; j < 4; j++) acc[mt][nt][j] = 0.0f;

        uint32_t Ab = AsA[b];
#pragma unroll
        for (int ks = 0; ks < 8; ks++) {
            int k0 = ks * 16;
            uint32_t af[2][4];
#pragma unroll
            for (int mt = 0; mt < 2; mt++)
                ldsm_x4(af[mt][0], af[mt][1], af[mt][2], af[mt][3],
                        Ab + (uint32_t)(a_off[mt] + k0) * 2);
            uint32_t bf[8][2];
#pragma unroll
            for (int p = 0; p < 4; p++)
                ldsm_x4(bf[2 * p][0], bf[2 * p][1], bf[2 * p + 1][0],
                        bf[2 * p + 1][1], WtA + (uint32_t)(b_off[p] + k0) * 2);
#pragma unroll
            for (int mt = 0; mt < 2; mt++)
#pragma unroll
                for (int nt = 0; nt < 8; nt++) mma_f16(acc[mt][nt], af[mt], bf[nt]);
        }

        int rowBase = tile * 128;
#pragma unroll
        for (int mt = 0; mt < 2; mt++) {
#pragma unroll
            for (int half = 0; half < 2; half++) {
                int r = rowBase + wm + mt * 16 + g + half * 8;
                if (r < N) {
#pragma unroll
                    for (int nt = 0; nt < 8; nt++) {
                        __half2 hv = __floats2half2_rn(acc[mt][nt][half * 2],
                                                       acc[mt][nt][half * 2 + 1]);
                        *(__half2*)&C[(size_t)r * F + wn + nt * 8 + tig * 2] = hv;
                    }
                }
            }
        }
        __syncthreads();
        b ^= 1;
    }

    // dinv tail (layer 1 only): deg excludes self-loop -> d = deg+1
    if (do_dinv) {
        for (int i = blockIdx.x * 256 + t; i < N; i += GEMM_GRID * 256)
            g_dinv[i] = rsqrtf((float)g_deg[i] + 1.0f);
    }
}

// ---------------------------------------------------------------------------
// Aggregation: one warp per node over ELL. Indices + dinv fetched by one
// lane-cooperative load and broadcast via shfl. Rows gathered as fp16 (256B).
// ---------------------------------------------------------------------------
template <int RELU, int OUTHALF>
__global__ void __launch_bounds__(256) k_agg(const uint16_t* __restrict__ XW,
                                             const float* __restrict__ bias,
                                             void* __restrict__ outp, int N) {
    int node = (blockIdx.x * blockDim.x + threadIdx.x) >> 5;
    int lane = threadIdx.x & 31;
    if (node >= N) return;

    float dc = g_dinv[node];
    int d = g_deg[node];
    int cnt = (d < ELLW) ? d : ELLW;

    const int* nb = g_ell + (size_t)node * ELLW;
    int idx0 = (lane < cnt) ? nb[lane] : 0;
    int idx1 = (lane + 32 < cnt) ? nb[lane + 32] : 0;
    float dv0 = (lane < cnt) ? g_dinv[idx0] : 0.0f;
    float dv1 = (lane + 32 < cnt) ? g_dinv[idx1] : 0.0f;

    uint2 sv = ((const uint2*)(XW + (size_t)node * F))[lane];
    float4 s = h4_to_f4(sv);
    float w = dc * dc;
    float4 acc = make_float4(s.x * w, s.y * w, s.z * w, s.w * w);

    for (int j = 0; j < cnt; j++) {
        int src = __shfl_sync(0xffffffffu, (j < 32) ? idx0 : idx1, j & 31);
        float ds = __shfl_sync(0xffffffffu, (j < 32) ? dv0 : dv1, j & 31);
        float nrm = ds * dc;
        uint2 uv = ((const uint2*)(XW + (size_t)src * F))[lane];
        float4 u = h4_to_f4(uv);
        acc.x += u.x * nrm;
        acc.y += u.y * nrm;
        acc.z += u.z * nrm;
        acc.w += u.w * nrm;
    }

    float4 bb = ((const float4*)bias)[lane];
    acc.x += bb.x; acc.y += bb.y; acc.z += bb.z; acc.w += bb.w;
    if (RELU) {
        acc.x = fmaxf(acc.x, 0.0f);
        acc.y = fmaxf(acc.y, 0.0f);
        acc.z = fmaxf(acc.z, 0.0f);
        acc.w = fmaxf(acc.w, 0.0f);
    }
    if (OUTHALF) {
        __half2 h01 = __floats2half2_rn(acc.x, acc.y);
        __half2 h23 = __floats2half2_rn(acc.z, acc.w);
        uint2 o;
        o.x = *(uint32_t*)&h01;
        o.y = *(uint32_t*)&h23;
        ((uint2*)((uint16_t*)outp + (size_t)node * F))[lane] = o;
    } else {
        ((float4*)((float*)outp + (size_t)node * F))[lane] = acc;
    }
}

// ---------------------------------------------------------------------------
extern "C" void kernel_launch(void* const* d_in, const int* in_sizes, int n_in,
                              void* d_out, int out_size) {
    const float* x = (const float*)d_in[0];
    const int* ei = (const int*)d_in[1];
    const float* W1 = (const float*)d_in[2];
    const float* b1 = (const float*)d_in[3];
    const float* W2 = (const float*)d_in[4];
    const float* b2 = (const float*)d_in[5];
    float* out = (float*)d_out;

    int N = in_sizes[0] / F;
    int E = in_sizes[1] / 2;

    uint16_t *xhp, *xwp, *hp;
    int* degp;
    cudaGetSymbolAddress((void**)&xhp, g_xh);
    cudaGetSymbolAddress((void**)&xwp, g_xw);
    cudaGetSymbolAddress((void**)&hp, g_h);
    cudaGetSymbolAddress((void**)&degp, g_deg);

    const int smem_bytes = 3 * 128 * PITCH_H * 2;  // Wt + 2 A buffers = 104448
    cudaFuncSetAttribute(k_gemm_tc, cudaFuncAttributeMaxDynamicSharedMemorySize,
                         smem_bytes);

    int ntiles = (N + 127) / 128;
    int agg_grid = (N + 7) / 8;
    int EB = (E + 255) / 256;
    int CONVB = (N * (F / 4) + 255) / 256;

    cudaMemsetAsync(degp, 0, (size_t)N * sizeof(int), 0);
    k_csr<<<EB + CONVB, 256>>>(ei, E, x, xhp, N, EB);

    // Layer 1
    k_gemm_tc<<<GEMM_GRID, 256, smem_bytes>>>((const __half*)xhp, W1, xwp, N,
                                              ntiles, 1);
    k_agg<1, 1><<<agg_grid, 256>>>(xwp, b1, hp, N);
    // Layer 2
    k_gemm_tc<<<GEMM_GRID, 256, smem_bytes>>>((const __half*)hp, W2, xwp, N,
                                              ntiles, 0);
    k_agg<0, 0><<<agg_grid, 256>>>(xwp, b2, out, N);
}

// round 8
// speedup vs baseline: 2.0395x; 1.0908x over previous
#include <cuda_runtime.h>
#include <cuda_fp16.h>
#include <cstdint>

#define F 128
#define MAXN 100000
#define PITCH_H 136     // smem pitch in halves: 272B ≡ 4 banks mod 32 -> ldmatrix conflict-free
#define ELLW 64
#define GEMM_GRID 304   // 2 blocks per SM

// Static device scratch (cudaMalloc is forbidden)
__device__ uint16_t g_xh[(size_t)MAXN * F];     // x converted to fp16
__device__ uint16_t g_xw[(size_t)MAXN * F];     // fp16 XW scratch
__device__ uint16_t g_h[(size_t)MAXN * F];      // fp16 hidden scratch
__device__ float    g_dinv[MAXN];
__device__ int      g_deg[MAXN];
__device__ int      g_ell[(size_t)MAXN * ELLW];

// ---------------------------------------------------------------------------
__device__ __forceinline__ void mma_f16(float* c, const uint32_t* a, const uint32_t* b) {
    asm volatile(
        "mma.sync.aligned.m16n8k16.row.col.f32.f16.f16.f32 "
        "{%0,%1,%2,%3}, {%4,%5,%6,%7}, {%8,%9}, {%0,%1,%2,%3};"
        : "+f"(c[0]), "+f"(c[1]), "+f"(c[2]), "+f"(c[3])
        : "r"(a[0]), "r"(a[1]), "r"(a[2]), "r"(a[3]), "r"(b[0]), "r"(b[1]));
}

__device__ __forceinline__ void ldsm_x4(uint32_t& r0, uint32_t& r1, uint32_t& r2,
                                        uint32_t& r3, uint32_t addr) {
    asm volatile("ldmatrix.sync.aligned.m8n8.x4.shared.b16 {%0,%1,%2,%3}, [%4];"
                 : "=r"(r0), "=r"(r1), "=r"(r2), "=r"(r3) : "r"(addr));
}

__device__ __forceinline__ void stsm_x2(uint32_t addr, uint32_t r0, uint32_t r1) {
    asm volatile("stmatrix.sync.aligned.m8n8.x2.shared.b16 [%0], {%1,%2};"
                 :: "r"(addr), "r"(r0), "r"(r1));
}

__device__ __forceinline__ void cp16(uint32_t dst, const void* src, int sz) {
    asm volatile("cp.async.cg.shared.global [%0], [%1], 16, %2;"
                 :: "r"(dst), "l"(src), "r"(sz));
}
__device__ __forceinline__ void cp_commit() { asm volatile("cp.async.commit_group;"); }
template <int NN>
__device__ __forceinline__ void cp_wait() {
    asm volatile("cp.async.wait_group %0;" :: "n"(NN));
}

__device__ __forceinline__ float4 h4_to_f4(uint2 v) {
    __half2 a = *(__half2*)&v.x;
    __half2 b = *(__half2*)&v.y;
    float2 fa = __half22float2(a);
    float2 fb = __half22float2(b);
    return make_float4(fa.x, fa.y, fb.x, fb.y);
}

// ---------------------------------------------------------------------------
// Fused: edge blocks build ELL (with inline int64/int32 detect); trailing
// blocks convert x fp32 -> fp16. deg pre-zeroed by memset.
// ---------------------------------------------------------------------------
__global__ void __launch_bounds__(256) k_csr(const int* __restrict__ ei, int E,
                                             const float* __restrict__ x,
                                             uint16_t* __restrict__ xh, int N,
                                             int EB) {
    int b = blockIdx.x;
    int t = threadIdx.x;
    if (b < EB) {
        __shared__ int s_is64;
        if (t < 32) {
            int n = (E < 16) ? E : 16;
            int bad = (t < n) ? (ei[2 * t + 1] != 0) : 0;
            bad = __any_sync(0xffffffffu, bad);
            if (t == 0) s_is64 = !bad;
        }
        __syncthreads();
        int is64 = s_is64;
        int e = b * 256 + t;
        if (e < E) {
            int r, c;
            if (is64) {
                r = ei[2 * e];
                c = ei[2 * E + 2 * e];
            } else {
                r = ei[e];
                c = ei[E + e];
            }
            int p = atomicAdd(&g_deg[c], 1);
            if (p < ELLW) g_ell[(size_t)c * ELLW + p] = r;
        }
    } else {
        int gid = (b - EB) * 256 + t;          // one float4 per thread
        int total = N * (F / 4);
        if (gid < total) {
            float4 v = ((const float4*)x)[gid];
            __half2 h01 = __floats2half2_rn(v.x, v.y);
            __half2 h23 = __floats2half2_rn(v.z, v.w);
            uint2 o;
            o.x = *(uint32_t*)&h01;
            o.y = *(uint32_t*)&h23;
            ((uint2*)xh)[gid] = o;
        }
    }
}

// ---------------------------------------------------------------------------
// Persistent double-buffered fp16 tensor-core GEMM:
// C[N,128] (fp16) = A[N,128] (fp16) * W[128,128] (fp32 -> fp16).
// mma.m16n8k16 + ldmatrix fragments; stmatrix epilogue staged through the
// consumed A buffer -> coalesced STG.128. 304 blocks (2/SM) x 256 threads.
// ---------------------------------------------------------------------------
__global__ void __launch_bounds__(256, 2) k_gemm_tc(const __half* __restrict__ A,
                                                    const float* __restrict__ W,
                                                    uint16_t* __restrict__ C,
                                                    int N, int ntiles, int do_dinv) {
    extern __shared__ char smraw[];
    __half* Wt = (__half*)smraw;                       // 128 * PITCH_H halves
    __half* As0 = (__half*)(smraw + 128 * PITCH_H * 2);
    __half* As1 = As0 + 128 * PITCH_H;
    uint32_t WtA = (uint32_t)__cvta_generic_to_shared(Wt);
    uint32_t AsA[2] = {(uint32_t)__cvta_generic_to_shared(As0),
                       (uint32_t)__cvta_generic_to_shared(As1)};
    int t = threadIdx.x;

    // Stage W: fp32 [k][n] -> fp16 Wt[n][k]
#pragma unroll
    for (int i = 0; i < 16; i++) {
        int lin = t + i * 256;             // 4096 float4 = 16384 floats
        int k = lin >> 5;
        int n4 = (lin & 31) * 4;
        float4 v = *(const float4*)&W[k * 128 + n4];
        Wt[(n4 + 0) * PITCH_H + k] = __float2half_rn(v.x);
        Wt[(n4 + 1) * PITCH_H + k] = __float2half_rn(v.y);
        Wt[(n4 + 2) * PITCH_H + k] = __float2half_rn(v.z);
        Wt[(n4 + 3) * PITCH_H + k] = __float2half_rn(v.w);
    }

    int wid = t >> 5;
    int lane = t & 31;
    int l16 = lane & 15;
    int wm = (wid & 3) * 32;   // warp m offset
    int wn = (wid >> 2) * 64;  // warp n offset

    // ldmatrix per-lane base offsets (halves)
    int arow = lane & 15;
    int akoff = (lane & 16) ? 8 : 0;
    int a_off[2];
#pragma unroll
    for (int mt = 0; mt < 2; mt++)
        a_off[mt] = (wm + mt * 16 + arow) * PITCH_H + akoff;
    int brow = (lane & 7) + ((lane & 16) ? 8 : 0);
    int bkoff = (lane & 8) ? 8 : 0;
    int b_off[4];
#pragma unroll
    for (int p = 0; p < 4; p++)
        b_off[p] = (wn + p * 16 + brow) * PITCH_H + bkoff;

    auto stage = [&](uint32_t dst, int tile) {
        int rowBase = tile * 128;
#pragma unroll
        for (int i = 0; i < 8; i++) {
            int lin = t + i * 256;         // 2048 x 16B chunks
            int r = lin >> 4;
            int c8 = lin & 15;
            int grow = rowBase + r;
            int cl = (grow < N) ? grow : (N - 1);
            cp16(dst + (uint32_t)(r * PITCH_H + c8 * 8) * 2,
                 (const char*)A + ((size_t)cl * F + c8 * 8) * 2,
                 (grow < N) ? 16 : 0);
        }
    };

    int tile0 = blockIdx.x;
    if (tile0 < ntiles) stage(AsA[0], tile0);
    cp_commit();

    int b = 0;
    for (int tile = tile0; tile < ntiles; tile += GEMM_GRID) {
        int next = tile + GEMM_GRID;
        if (next < ntiles) {
            stage(AsA[b ^ 1], next);
            cp_commit();
            cp_wait<1>();
        } else {
            cp_commit();
            cp_wait<0>();
        }
        __syncthreads();

        float acc[2][8][4];
#pragma unroll
        for (int mt = 0; mt < 2; mt++)
#pragma unroll
            for (int nt = 0; nt < 8; nt++)
#pragma unroll
                for (int j = 0; j < 4; j++) acc[mt][nt][j] = 0.0f;

        uint32_t Ab = AsA[b];
#pragma unroll
        for (int ks = 0; ks < 8; ks++) {
            int k0 = ks * 16;
            uint32_t af[2][4];
#pragma unroll
            for (int mt = 0; mt < 2; mt++)
                ldsm_x4(af[mt][0], af[mt][1], af[mt][2], af[mt][3],
                        Ab + (uint32_t)(a_off[mt] + k0) * 2);
            uint32_t bf[8][2];
#pragma unroll
            for (int p = 0; p < 4; p++)
                ldsm_x4(bf[2 * p][0], bf[2 * p][1], bf[2 * p + 1][0],
                        bf[2 * p + 1][1], WtA + (uint32_t)(b_off[p] + k0) * 2);
#pragma unroll
            for (int mt = 0; mt < 2; mt++)
#pragma unroll
                for (int nt = 0; nt < 8; nt++) mma_f16(acc[mt][nt], af[mt], bf[nt]);
        }
        __syncthreads();  // everyone done reading As[b]; reuse as epilogue staging

        // stmatrix: acc -> fp16 tile in As[b] (lanes 0-15 supply row addrs)
#pragma unroll
        for (int mt = 0; mt < 2; mt++) {
#pragma unroll
            for (int nt = 0; nt < 8; nt++) {
                uint32_t addr = Ab +
                    (uint32_t)((wm + mt * 16 + l16) * PITCH_H + wn + nt * 8) * 2;
                __half2 lo = __floats2half2_rn(acc[mt][nt][0], acc[mt][nt][1]);
                __half2 hi = __floats2half2_rn(acc[mt][nt][2], acc[mt][nt][3]);
                stsm_x2(addr, *(uint32_t*)&lo, *(uint32_t*)&hi);
            }
        }
        __syncthreads();

        // Coalesced write-out: 2048 uint4, 8 per thread
        int rowBase = tile * 128;
        const __half* Sb = (b == 0) ? As0 : As1;
#pragma unroll
        for (int i = 0; i < 8; i++) {
            int lin = t + i * 256;
            int r = lin >> 4;
            int c16 = lin & 15;
            int grow = rowBase + r;
            if (grow < N) {
                uint4 v = *(const uint4*)&Sb[r * PITCH_H + c16 * 8];
                *(uint4*)&C[(size_t)grow * F + c16 * 8] = v;
            }
        }
        __syncthreads();  // staging free before next prefetch targets it
        b ^= 1;
    }

    // dinv tail (layer 1 only): deg excludes self-loop -> d = deg+1
    if (do_dinv) {
        for (int i = blockIdx.x * 256 + t; i < N; i += GEMM_GRID * 256)
            g_dinv[i] = rsqrtf((float)g_deg[i] + 1.0f);
    }
}

// ---------------------------------------------------------------------------
// Aggregation: one warp per node over ELL. Indices + dinv fetched by one
// lane-cooperative load + shfl broadcast; gathers batched 2-wide for MLP.
// ---------------------------------------------------------------------------
template <int RELU, int OUTHALF>
__global__ void __launch_bounds__(256) k_agg(const uint16_t* __restrict__ XW,
                                             const float* __restrict__ bias,
                                             void* __restrict__ outp, int N) {
    int node = (blockIdx.x * blockDim.x + threadIdx.x) >> 5;
    int lane = threadIdx.x & 31;
    if (node >= N) return;

    float dc = g_dinv[node];
    int d = g_deg[node];
    int cnt = (d < ELLW) ? d : ELLW;

    const int* nb = g_ell + (size_t)node * ELLW;
    int idx0 = (lane < cnt) ? nb[lane] : 0;
    int idx1 = (lane + 32 < cnt) ? nb[lane + 32] : 0;
    float dv0 = (lane < cnt) ? g_dinv[idx0] : 0.0f;
    float dv1 = (lane + 32 < cnt) ? g_dinv[idx1] : 0.0f;

    uint2 sv = ((const uint2*)(XW + (size_t)node * F))[lane];
    float4 s = h4_to_f4(sv);
    float w = dc * dc;
    float4 acc = make_float4(s.x * w, s.y * w, s.z * w, s.w * w);

    int j = 0;
    for (; j + 2 <= cnt; j += 2) {
        int sa = __shfl_sync(0xffffffffu, (j < 32) ? idx0 : idx1, j & 31);
        float da = __shfl_sync(0xffffffffu, (j < 32) ? dv0 : dv1, j & 31);
        int jb = j + 1;
        int sb = __shfl_sync(0xffffffffu, (jb < 32) ? idx0 : idx1, jb & 31);
        float db = __shfl_sync(0xffffffffu, (jb < 32) ? dv0 : dv1, jb & 31);
        uint2 ua = ((const uint2*)(XW + (size_t)sa * F))[lane];
        uint2 ub = ((const uint2*)(XW + (size_t)sb * F))[lane];
        float na = da * dc;
        float nbm = db * dc;
        float4 fa = h4_to_f4(ua);
        float4 fb = h4_to_f4(ub);
        acc.x += fa.x * na + fb.x * nbm;
        acc.y += fa.y * na + fb.y * nbm;
        acc.z += fa.z * na + fb.z * nbm;
        acc.w += fa.w * na + fb.w * nbm;
    }
    if (j < cnt) {
        int sa = __shfl_sync(0xffffffffu, (j < 32) ? idx0 : idx1, j & 31);
        float da = __shfl_sync(0xffffffffu, (j < 32) ? dv0 : dv1, j & 31);
        uint2 ua = ((const uint2*)(XW + (size_t)sa * F))[lane];
        float na = da * dc;
        float4 fa = h4_to_f4(ua);
        acc.x += fa.x * na;
        acc.y += fa.y * na;
        acc.z += fa.z * na;
        acc.w += fa.w * na;
    }

    float4 bb = ((const float4*)bias)[lane];
    acc.x += bb.x; acc.y += bb.y; acc.z += bb.z; acc.w += bb.w;
    if (RELU) {
        acc.x = fmaxf(acc.x, 0.0f);
        acc.y = fmaxf(acc.y, 0.0f);
        acc.z = fmaxf(acc.z, 0.0f);
        acc.w = fmaxf(acc.w, 0.0f);
    }
    if (OUTHALF) {
        __half2 h01 = __floats2half2_rn(acc.x, acc.y);
        __half2 h23 = __floats2half2_rn(acc.z, acc.w);
        uint2 o;
        o.x = *(uint32_t*)&h01;
        o.y = *(uint32_t*)&h23;
        ((uint2*)((uint16_t*)outp + (size_t)node * F))[lane] = o;
    } else {
        ((float4*)((float*)outp + (size_t)node * F))[lane] = acc;
    }
}

// ---------------------------------------------------------------------------
extern "C" void kernel_launch(void* const* d_in, const int* in_sizes, int n_in,
                              void* d_out, int out_size) {
    const float* x = (const float*)d_in[0];
    const int* ei = (const int*)d_in[1];
    const float* W1 = (const float*)d_in[2];
    const float* b1 = (const float*)d_in[3];
    const float* W2 = (const float*)d_in[4];
    const float* b2 = (const float*)d_in[5];
    float* out = (float*)d_out;

    int N = in_sizes[0] / F;
    int E = in_sizes[1] / 2;

    uint16_t *xhp, *xwp, *hp;
    int* degp;
    cudaGetSymbolAddress((void**)&xhp, g_xh);
    cudaGetSymbolAddress((void**)&xwp, g_xw);
    cudaGetSymbolAddress((void**)&hp, g_h);
    cudaGetSymbolAddress((void**)&degp, g_deg);

    const int smem_bytes = 3 * 128 * PITCH_H * 2;  // Wt + 2 A buffers = 104448
    cudaFuncSetAttribute(k_gemm_tc, cudaFuncAttributeMaxDynamicSharedMemorySize,
                         smem_bytes);

    int ntiles = (N + 127) / 128;
    int agg_grid = (N + 7) / 8;
    int EB = (E + 255) / 256;
    int CONVB = (N * (F / 4) + 255) / 256;

    cudaMemsetAsync(degp, 0, (size_t)N * sizeof(int), 0);
    k_csr<<<EB + CONVB, 256>>>(ei, E, x, xhp, N, EB);

    // Layer 1
    k_gemm_tc<<<GEMM_GRID, 256, smem_bytes>>>((const __half*)xhp, W1, xwp, N,
                                              ntiles, 1);
    k_agg<1, 1><<<agg_grid, 256>>>(xwp, b1, hp, N);
    // Layer 2
    k_gemm_tc<<<GEMM_GRID, 256, smem_bytes>>>((const __half*)hp, W2, xwp, N,
                                              ntiles, 0);
    k_agg<0, 0><<<agg_grid, 256>>>(xwp, b2, out, N);
}